// round 15
// baseline (speedup 1.0000x reference)
#include <cuda_runtime.h>
#include <cuda_fp16.h>
#include <math.h>
#include <stdint.h>

#define B_ 256
#define L_ 512
#define H_ 1024
#define S_ 16
#define HOR_ 64
#define PRED_ELEMS (B_*HOR_*L_)

typedef __half f16;

// ---------------- fp32 scratch ----------------------------------------------
__device__ float g_q[B_*H_];
__device__ float g_kmem[S_*H_];
__device__ float g_vmem[S_*H_];
__device__ float g_ctx[B_*H_];
__device__ float g_context[B_*L_];
__device__ float g_pgh[B_*H_];
__device__ float g_prior[B_*L_];
__device__ float g_c0[B_*H_];
__device__ float g_c1[B_*H_];

// ---------------- fp16 scratch ------------------------------------------------
// x/t: hi+lo (exact). h0/h1: single fp16 (tanh-bounded). weights: single fp16.
__device__ __align__(16) f16 g_xh[B_*L_],  g_xl[B_*L_];
__device__ __align__(16) f16 g_h0[2][B_*H_];
__device__ __align__(16) f16 g_h1[2][B_*H_];
__device__ __align__(16) f16 g_th[B_*H_],  g_tl[B_*H_];
__device__ __align__(16) f16 g_wih0[4*H_*L_];
__device__ __align__(16) f16 g_whh0[4*H_*H_];
__device__ __align__(16) f16 g_wih1[4*H_*H_];
__device__ __align__(16) f16 g_whh1[4*H_*H_];
__device__ __align__(16) f16 g_opW1[H_*H_];
__device__ __align__(16) f16 g_opW2[L_*H_];

// ---------------- hierarchical grid barrier (256 CTAs: 8 x 32) ---------------
__device__ unsigned g_cnt[8*32];
__device__ unsigned g_cnt2 = 0;
__device__ unsigned g_gen  = 0;

// ---------------- low-level helpers ------------------------------------------
__device__ __forceinline__ uint32_t smem_u32(const void* p) {
    uint32_t a;
    asm("{ .reg .u64 t; cvta.to.shared.u64 t, %1; cvt.u32.u64 %0, t; }" : "=r"(a) : "l"(p));
    return a;
}

#define CP_ASYNC16(d, s) \
    asm volatile("cp.async.cg.shared.global [%0], [%1], 16;" :: "r"(d), "l"(s))
#define CP_COMMIT()  asm volatile("cp.async.commit_group;" ::: "memory")

__device__ __forceinline__ void ldm_x4(uint32_t* r, uint32_t addr) {
    asm volatile("ldmatrix.sync.aligned.m8n8.x4.shared.b16 {%0,%1,%2,%3}, [%4];"
                 : "=r"(r[0]), "=r"(r[1]), "=r"(r[2]), "=r"(r[3]) : "r"(addr));
}

__device__ __forceinline__ void mma16816(float* d, const uint32_t* a, const uint32_t* b) {
    asm volatile(
        "mma.sync.aligned.m16n8k16.row.col.f32.f16.f16.f32 "
        "{%0,%1,%2,%3}, {%4,%5,%6,%7}, {%8,%9}, {%0,%1,%2,%3};"
        : "+f"(d[0]), "+f"(d[1]), "+f"(d[2]), "+f"(d[3])
        : "r"(a[0]), "r"(a[1]), "r"(a[2]), "r"(a[3]), "r"(b[0]), "r"(b[1]));
}

__device__ __forceinline__ void grid_sync() {
    __syncthreads();
    if (threadIdx.x == 0) {
        volatile unsigned* genp = (volatile unsigned*)&g_gen;
        const unsigned gen = *genp;
        __threadfence();
        unsigned old = atomicAdd(&g_cnt[(blockIdx.x & 7) * 32], 1u);
        bool flipped = false;
        if (old == 31u) {
            unsigned old2 = atomicAdd(&g_cnt2, 1u);
            if (old2 == 7u) {
                #pragma unroll
                for (int i = 0; i < 8; i++) g_cnt[i * 32] = 0u;
                g_cnt2 = 0u;
                __threadfence();
                *genp = gen + 1u;
                flipped = true;
            }
        }
        if (!flipped) {
            while (*genp == gen) { }
        }
        __threadfence();
    }
    __syncthreads();
}

// ---------------- device GEMM core (dual source, 4 warps as 2x2) -------------
// acc += A1@W1^T (+A1lo@W1^T if lo_mask&1) + A2@W2^T (+A2lo@W2^T if lo_mask&2)
#define PSTRIDE 40
#define P_SMEM (3 * (2*64 + 64) * PSTRIDE * 2)   // 46080 (gates 64x64 config)

template<int BM, int BN>
__device__ __forceinline__ void gemm_dual(
    uint32_t sb, int tid,
    const f16* __restrict__ Ah1, const f16* __restrict__ Al1, int lda1,
    const f16* __restrict__ W1, int ldw1, int nc1,
    const f16* __restrict__ Ah2, const f16* __restrict__ Al2, int lda2,
    const f16* __restrict__ W2, int ldw2, int nc2,
    int lo_mask,
    float (&acc)[BM/32][2*(BN/32)][4])
{
    constexpr int MI  = BM / 32;
    constexpr int NJ  = BN / 32;
    constexpr int AHo = 0;
    constexpr int ALo = BM * PSTRIDE;
    constexpr int Wo  = 2 * BM * PSTRIDE;
    constexpr int STAGE_B = (2 * BM + BN) * PSTRIDE * 2;

    const int lane = tid & 31, wid = tid >> 5;
    const int warp_m = wid >> 1, warp_n = wid & 1;
    const int nc = nc1 + nc2;

    auto do_load = [&](int c) {
        const int src = (c < nc1) ? 0 : 1;
        const int k0  = ((src == 0) ? c : (c - nc1)) << 5;
        const bool uselo = src ? ((lo_mask & 2) != 0) : ((lo_mask & 1) != 0);
        const f16* Ah = src ? Ah2 : Ah1;
        const f16* Al = src ? Al2 : Al1;
        const f16* W  = src ? W2  : W1;
        const int lda = src ? lda2 : lda1;
        const int ldw = src ? ldw2 : ldw1;
        const uint32_t st = sb + (uint32_t)(c % 3) * STAGE_B;

        constexpr int T16 = (2 * BM + BN) * 4;
        #pragma unroll
        for (int it = 0; it < T16 / 128; it++) {
            int idx = tid + it * 128;
            int row = idx >> 2, ch = idx & 3;
            const f16* g; int soff;
            if (row < BM)        {               g = Ah + (size_t)row * lda; soff = AHo + row * PSTRIDE; }
            else if (row < 2*BM) {
                if (!uselo) continue;            // lo tile unused for this chunk
                int r = row - BM;  g = Al + (size_t)r * lda; soff = ALo + r * PSTRIDE;
            }
            else                 { int r = row - 2*BM; g = W + (size_t)r * ldw; soff = Wo + r * PSTRIDE; }
            CP_ASYNC16(st + (uint32_t)(soff + ch * 8) * 2, g + k0 + ch * 8);
        }
        CP_COMMIT();
    };

    do_load(0);
    if (nc > 1) do_load(1);

    const int a_row = warp_m * (MI * 16) + (lane & 15);
    const int a_kof = (lane >> 4) << 3;
    const int b_row = warp_n * (NJ * 16) + ((lane >> 4) << 3) + (lane & 7);
    const int b_kof = ((lane >> 3) & 1) << 3;

    for (int c = 0; c < nc; c++) {
        if (c + 1 < nc) asm volatile("cp.async.wait_group 1;" ::: "memory");
        else            asm volatile("cp.async.wait_group 0;" ::: "memory");
        __syncthreads();

        if (c + 2 < nc) do_load(c + 2);

        const uint32_t st = sb + (uint32_t)(c % 3) * STAGE_B;
        const bool uselo = (c < nc1) ? ((lo_mask & 1) != 0) : ((lo_mask & 2) != 0);

        #pragma unroll
        for (int k16 = 0; k16 < 2; k16++) {
            const int kk = k16 * 16;
            uint32_t ah[MI][4], al[MI][4], bw[NJ][4];
            #pragma unroll
            for (int mi = 0; mi < MI; mi++) {
                ldm_x4(ah[mi], st + (uint32_t)((AHo + (a_row + mi*16) * PSTRIDE + kk + a_kof) * 2));
                if (uselo)
                    ldm_x4(al[mi], st + (uint32_t)((ALo + (a_row + mi*16) * PSTRIDE + kk + a_kof) * 2));
            }
            #pragma unroll
            for (int g = 0; g < NJ; g++)
                ldm_x4(bw[g], st + (uint32_t)((Wo + (b_row + g*16) * PSTRIDE + kk + b_kof) * 2));
            #pragma unroll
            for (int mi = 0; mi < MI; mi++)
                #pragma unroll
                for (int nj = 0; nj < 2*NJ; nj++) {
                    const int g = nj >> 1, o = (nj & 1) * 2;
                    mma16816(acc[mi][nj], ah[mi], &bw[g][o]);
                    if (uselo) mma16816(acc[mi][nj], al[mi], &bw[g][o]);
                }
        }
    }
    __syncthreads();
}

template<int MI, int NJ2>
__device__ __forceinline__ void zero_acc(float (&acc)[MI][NJ2][4]) {
    #pragma unroll
    for (int i = 0; i < MI; i++)
        #pragma unroll
        for (int j = 0; j < NJ2; j++)
            #pragma unroll
            for (int r = 0; r < 4; r++) acc[i][j][r] = 0.f;
}

// fused LSTM cell epilogue (64x64 tiles, warp 32x32; col n = 4*j + gate)
// writes h as single fp16.
__device__ __forceinline__ void cell_epi(
    float (&acc)[2][4][4], int tid, int m0, int n0,
    const float* __restrict__ b1, const float* __restrict__ b2,
    const float* __restrict__ cin, float* __restrict__ cout,
    f16* __restrict__ Oh)
{
    const int lane = tid & 31, wid = tid >> 5;
    const int warp_m = wid >> 1, warp_n = wid & 1;
    const int m_base = m0 + warp_m * 32;
    const int n_base = n0 + warp_n * 32;
    #pragma unroll
    for (int mi = 0; mi < 2; mi++) {
        #pragma unroll
        for (int nj = 0; nj < 4; nj++) {
            const int c0 = n_base + nj * 8 + (lane & 3) * 2;
            const int bi0 = (c0 & 3) * H_ + (c0 >> 2);
            const int bi1 = ((c0 + 1) & 3) * H_ + ((c0 + 1) >> 2);
            const float bias0 = b1[bi0] + b2[bi0];
            const float bias1 = b1[bi1] + b2[bi1];
            #pragma unroll
            for (int half = 0; half < 2; half++) {
                const int row = m_base + mi * 16 + (lane >> 2) + half * 8;
                float v0 = acc[mi][nj][half*2 + 0] + bias0;
                float v1 = acc[mi][nj][half*2 + 1] + bias1;
                float p0 = __shfl_xor_sync(0xffffffffu, v0, 1);
                float p1 = __shfl_xor_sync(0xffffffffu, v1, 1);
                if ((lane & 1) == 0) {
                    const int j   = c0 >> 2;
                    const int idx = row * H_ + j;
                    float ig = 1.f / (1.f + expf(-v0));
                    float fg = 1.f / (1.f + expf(-v1));
                    float gg = tanhf(p0);
                    float og = 1.f / (1.f + expf(-p1));
                    float cv = fg * cin[idx] + ig * gg;
                    float hv = og * tanhf(cv);
                    cout[idx] = cv;
                    Oh[idx] = __float2half(hv);
                }
            }
        }
    }
}

// standard epilogue: bias (+relu), optional fp32 C, optional fp16 hi/lo split
template<int MI, int NJ>
__device__ __forceinline__ void std_epi(
    float (&acc)[MI][2*NJ][4], int tid, int m0, int n0,
    const float* __restrict__ b,
    float* __restrict__ C, int ldc,
    f16* __restrict__ Oh, f16* __restrict__ Ol, int ldo, int relu)
{
    const int lane = tid & 31, wid = tid >> 5;
    const int warp_m = wid >> 1, warp_n = wid & 1;
    const int m_base = m0 + warp_m * (MI * 16);
    const int n_base = n0 + warp_n * (NJ * 16);
    #pragma unroll
    for (int mi = 0; mi < MI; mi++) {
        #pragma unroll
        for (int nj = 0; nj < 2*NJ; nj++) {
            const int col = n_base + nj * 8 + (lane & 3) * 2;
            const float bias0 = b[col];
            const float bias1 = b[col + 1];
            #pragma unroll
            for (int half = 0; half < 2; half++) {
                const int row = m_base + mi * 16 + (lane >> 2) + half * 8;
                float v0 = acc[mi][nj][half*2 + 0] + bias0;
                float v1 = acc[mi][nj][half*2 + 1] + bias1;
                if (relu) { v0 = fmaxf(v0, 0.f); v1 = fmaxf(v1, 0.f); }
                if (C)
                    *reinterpret_cast<float2*>(C + (size_t)row * ldc + col) =
                        make_float2(v0, v1);
                if (Oh) {
                    f16 h0 = __float2half(v0);
                    f16 h1 = __float2half(v1);
                    f16 l0 = __float2half(v0 - __half2float(h0));
                    f16 l1 = __float2half(v1 - __half2float(h1));
                    f16 hp[2] = {h0, h1}, lp[2] = {l0, l1};
                    *reinterpret_cast<uint32_t*>(Oh + (size_t)row * ldo + col) =
                        *reinterpret_cast<uint32_t*>(hp);
                    *reinterpret_cast<uint32_t*>(Ol + (size_t)row * ldo + col) =
                        *reinterpret_cast<uint32_t*>(lp);
                }
            }
        }
    }
}

// ---------------- persistent rollout kernel ----------------------------------
__global__ void __launch_bounds__(128, 2)
rollout_kernel(const float* __restrict__ bih0, const float* __restrict__ bhh0,
               const float* __restrict__ bih1, const float* __restrict__ bhh1,
               const float* __restrict__ opb1, const float* __restrict__ opb2,
               float* __restrict__ out)
{
    extern __shared__ __align__(16) char smem[];
    const uint32_t sb = smem_u32(smem);
    const int tid = threadIdx.x;
    const int cta = blockIdx.x;

    const int gm0 = (cta & 3) * 64;
    const int gn0 = (cta >> 2) * 64;
    const int o1m = (cta & 7) * 32, o1n = (cta >> 3) * 32;
    const int o2m = (cta & 7) * 32, o2n = (cta >> 3) * 32;

    for (int s = 0; s < HOR_; s++) {
        const int p = s & 1, pn = p ^ 1;

        // ---- phase 1: gates0 (x@wih0 [2t] + h0@whh0 [1t]) + cell ----
        {
            float acc[2][4][4];
            zero_acc(acc);
            gemm_dual<64,64>(sb, tid,
                g_xh + (size_t)gm0*L_, g_xl + (size_t)gm0*L_, L_,
                g_wih0 + (size_t)gn0*L_, L_, L_/32,
                g_h0[p] + (size_t)gm0*H_, g_h0[p] + (size_t)gm0*H_, H_,
                g_whh0 + (size_t)gn0*H_, H_, H_/32,
                /*lo_mask=*/1,
                acc);
            cell_epi(acc, tid, gm0, gn0, bih0, bhh0, g_c0, g_c0, g_h0[pn]);
        }
        grid_sync();

        // ---- phase 2: gates1 (h0@wih1 [1t] + h1@whh1 [1t]) + cell ----
        {
            float acc[2][4][4];
            zero_acc(acc);
            gemm_dual<64,64>(sb, tid,
                g_h0[pn] + (size_t)gm0*H_, g_h0[pn] + (size_t)gm0*H_, H_,
                g_wih1 + (size_t)gn0*H_, H_, H_/32,
                g_h1[p] + (size_t)gm0*H_, g_h1[p] + (size_t)gm0*H_, H_,
                g_whh1 + (size_t)gn0*H_, H_, H_/32,
                /*lo_mask=*/0,
                acc);
            cell_epi(acc, tid, gm0, gn0, bih1, bhh1, g_c1, g_c1, g_h1[pn]);
        }
        grid_sync();

        // ---- phase 3: op1 = relu(h1 @ opW1^T + b1) [1t] -> th/tl ----
        {
            float acc[1][2][4];
            zero_acc(acc);
            gemm_dual<32,32>(sb, tid,
                g_h1[pn] + (size_t)o1m*H_, g_h1[pn] + (size_t)o1m*H_, H_,
                g_opW1 + (size_t)o1n*H_, H_, H_/32,
                nullptr, nullptr, 0, nullptr, 0, 0,
                /*lo_mask=*/0,
                acc);
            std_epi<1,1>(acc, tid, o1m, o1n, opb1, nullptr, 0, g_th, g_tl, H_, 1);
        }
        grid_sync();

        // ---- phase 4: op2 = t @ opW2^T + b2 [2t] -> out + x split ----
        if (cta < 128) {
            float acc[1][2][4];
            zero_acc(acc);
            gemm_dual<32,32>(sb, tid,
                g_th + (size_t)o2m*H_, g_tl + (size_t)o2m*H_, H_,
                g_opW2 + (size_t)o2n*H_, H_, H_/32,
                nullptr, nullptr, 0, nullptr, 0, 0,
                /*lo_mask=*/1,
                acc);
            std_epi<1,1>(acc, tid, o2m, o2n, opb2,
                         out + (size_t)s * L_, HOR_*L_, g_xh, g_xl, L_, 0);
        }
        grid_sync();
    }
}

// ---------------- fp32 GEMM (prologue only) ---------------------------------
template<int BM,int BN,int BK,int TM,int TN,int NT>
__global__ __launch_bounds__(NT)
void gemm2_kernel(const float* __restrict__ A1, int lda1,
                  const float* __restrict__ W1, int ldw1, int K1,
                  const float* __restrict__ A2, int lda2,
                  const float* __restrict__ W2, int ldw2, int K2,
                  const float* __restrict__ b1, const float* __restrict__ b2,
                  float* __restrict__ C, int ldc, int M, int N, int relu)
{
    __shared__ __align__(16) float As[BK][BM+4];
    __shared__ __align__(16) float Ws[BK][BN+4];
    const int tid = threadIdx.x;
    const int m0  = blockIdx.y * BM;
    const int n0  = blockIdx.x * BN;
    const int m0t = (tid / (BN/TN)) * TM;
    const int n0t = (tid % (BN/TN)) * TN;
    float acc[TM][TN];
    #pragma unroll
    for (int i = 0; i < TM; i++)
        #pragma unroll
        for (int j = 0; j < TN; j++) acc[i][j] = 0.f;
    for (int src = 0; src < 2; src++) {
        const float* A = src ? A2 : A1;
        if (A == nullptr) break;
        const float* W = src ? W2 : W1;
        const int lda = src ? lda2 : lda1;
        const int ldw = src ? ldw2 : ldw1;
        const int K   = src ? K2   : K1;
        for (int k0 = 0; k0 < K; k0 += BK) {
            constexpr int A4 = BM*BK/4;
            #pragma unroll
            for (int it = 0; it < A4/NT; it++) {
                int i4 = tid + NT*it;
                int row = i4 / (BK/4), cv = i4 % (BK/4);
                float4 val = make_float4(0,0,0,0);
                int gr = m0 + row;
                if (gr < M) val = *reinterpret_cast<const float4*>(A + (size_t)gr*lda + k0 + cv*4);
                As[cv*4+0][row]=val.x; As[cv*4+1][row]=val.y;
                As[cv*4+2][row]=val.z; As[cv*4+3][row]=val.w;
            }
            constexpr int W4 = BN*BK/4;
            #pragma unroll
            for (int it = 0; it < W4/NT; it++) {
                int i4 = tid + NT*it;
                int row = i4 / (BK/4), cv = i4 % (BK/4);
                float4 val = *reinterpret_cast<const float4*>(W + (size_t)(n0+row)*ldw + k0 + cv*4);
                Ws[cv*4+0][row]=val.x; Ws[cv*4+1][row]=val.y;
                Ws[cv*4+2][row]=val.z; Ws[cv*4+3][row]=val.w;
            }
            __syncthreads();
            #pragma unroll
            for (int kk = 0; kk < BK; kk++) {
                float a[TM], bb[TN];
                #pragma unroll
                for (int i = 0; i < TM; i += 4) {
                    float4 t = *reinterpret_cast<const float4*>(&As[kk][m0t+i]);
                    a[i]=t.x; a[i+1]=t.y; a[i+2]=t.z; a[i+3]=t.w;
                }
                #pragma unroll
                for (int j = 0; j < TN; j += 4) {
                    float4 t = *reinterpret_cast<const float4*>(&Ws[kk][n0t+j]);
                    bb[j]=t.x; bb[j+1]=t.y; bb[j+2]=t.z; bb[j+3]=t.w;
                }
                #pragma unroll
                for (int i = 0; i < TM; i++)
                    #pragma unroll
                    for (int j = 0; j < TN; j++)
                        acc[i][j] = fmaf(a[i], bb[j], acc[i][j]);
            }
            __syncthreads();
        }
    }
    #pragma unroll
    for (int j = 0; j < TN; j++) {
        int gn = n0 + n0t + j;
        float bias = (b1 ? b1[gn] : 0.f) + (b2 ? b2[gn] : 0.f);
        #pragma unroll
        for (int i = 0; i < TM; i++) {
            int gm = m0 + m0t + i;
            if (gm < M) {
                float vo = acc[i][j] + bias;
                if (relu) vo = fmaxf(vo, 0.f);
                C[(size_t)gm*ldc + gn] = vo;
            }
        }
    }
}

// ---------------- attention --------------------------------------------------
__global__ __launch_bounds__(256)
void attn_kernel(const float* __restrict__ q, const float* __restrict__ k,
                 const float* __restrict__ v, float* __restrict__ ctx)
{
    const int b = blockIdx.x, tid = threadIdx.x;
    const int lane = tid & 31, wid = tid >> 5;
    float p[S_];
    #pragma unroll
    for (int s = 0; s < S_; s++) p[s] = 0.f;
    for (int e = tid; e < H_; e += 256) {
        float qv = q[b*H_ + e];
        #pragma unroll
        for (int s = 0; s < S_; s++) p[s] = fmaf(qv, k[s*H_ + e], p[s]);
    }
    #pragma unroll
    for (int s = 0; s < S_; s++)
        #pragma unroll
        for (int off = 16; off > 0; off >>= 1)
            p[s] += __shfl_down_sync(0xffffffffu, p[s], off);
    __shared__ float sred[S_*8];
    __shared__ float wts[S_];
    if (lane == 0)
        #pragma unroll
        for (int s = 0; s < S_; s++) sred[s*8 + wid] = p[s];
    __syncthreads();
    if (tid == 0) {
        float sc[S_]; float mx = -1e30f;
        #pragma unroll
        for (int s = 0; s < S_; s++) {
            float a = 0.f;
            #pragma unroll
            for (int w = 0; w < 8; w++) a += sred[s*8 + w];
            sc[s] = a * (1.0f/32.0f);
            mx = fmaxf(mx, sc[s]);
        }
        float sum = 0.f;
        #pragma unroll
        for (int s = 0; s < S_; s++) { sc[s] = expf(sc[s]-mx); sum += sc[s]; }
        float inv = 1.f/sum;
        #pragma unroll
        for (int s = 0; s < S_; s++) wts[s] = sc[s]*inv;
    }
    __syncthreads();
    for (int j = tid; j < H_; j += 256) {
        float a = 0.f;
        #pragma unroll
        for (int s = 0; s < S_; s++) a = fmaf(wts[s], v[s*H_ + j], a);
        ctx[b*H_ + j] = a;
    }
}

// ---------------- converts ------------------------------------------------------
__global__ __launch_bounds__(256)
void split_kernel(const float* __restrict__ src, f16* __restrict__ hi,
                  f16* __restrict__ lo, int n)
{
    int i = blockIdx.x*blockDim.x + threadIdx.x;
    if (i < n) {
        float v = src[i];
        f16 h = __float2half(v);
        hi[i] = h;
        lo[i] = __float2half(v - __half2float(h));
    }
}

// gate-interleaved fp16 weight convert: out row n = 4*j + g <- in row g*H + j
__global__ __launch_bounds__(256)
void conv_gate_kernel(const float* __restrict__ src, f16* __restrict__ dst,
                      int K, int n)
{
    int i = blockIdx.x*blockDim.x + threadIdx.x;
    if (i < n) {
        int row = i / K, k = i - row * K;
        int orow = (row & 3) * H_ + (row >> 2);
        dst[i] = __float2half(src[(size_t)orow * K + k]);
    }
}

__global__ __launch_bounds__(256)
void conv_kernel(const float* __restrict__ src, f16* __restrict__ dst, int n)
{
    int i = blockIdx.x*blockDim.x + threadIdx.x;
    if (i < n) dst[i] = __float2half(src[i]);
}

__global__ __launch_bounds__(256)
void zero_state_kernel()
{
    int i = blockIdx.x*blockDim.x + threadIdx.x;
    if (i < B_*H_) {
        g_c0[i] = 0.f; g_c1[i] = 0.f;
        f16 z = __float2half(0.f);
        g_h0[0][i] = z; g_h1[0][i] = z;
        g_h0[1][i] = z; g_h1[1][i] = z;
    }
    if (i < 8*32) g_cnt[i] = 0;
    if (i == 0) { g_cnt2 = 0; g_gen = 0; }
}

// ---------------- host helpers -------------------------------------------------
static inline void gemm_small(const float* A1,int lda1,const float* W1,int ldw1,int K1,
                              const float* A2,int lda2,const float* W2,int ldw2,int K2,
                              const float* b1,const float* b2,
                              float* C,int ldc,int M,int N,int relu)
{
    dim3 grid(N/32, (M + 63)/64);
    gemm2_kernel<64,32,16,4,4,128><<<grid,128>>>(A1,lda1,W1,ldw1,K1,
                                                 A2,lda2,W2,ldw2,K2,
                                                 b1,b2,C,ldc,M,N,relu);
}

extern "C" void kernel_launch(void* const* d_in, const int* in_sizes, int n_in,
                              void* d_out, int out_size)
{
    (void)in_sizes; (void)n_in;
    const float* cs   = (const float*)d_in[0];
    const float* mem  = (const float*)d_in[2];
    const float* qW   = (const float*)d_in[3];
    const float* qb   = (const float*)d_in[4];
    const float* kW   = (const float*)d_in[5];
    const float* kb   = (const float*)d_in[6];
    const float* vW   = (const float*)d_in[7];
    const float* vb   = (const float*)d_in[8];
    const float* moW  = (const float*)d_in[9];
    const float* mob  = (const float*)d_in[10];
    const float* pgW1 = (const float*)d_in[11];
    const float* pgb1 = (const float*)d_in[12];
    const float* pgW2 = (const float*)d_in[13];
    const float* pgb2 = (const float*)d_in[14];
    const float* wih0 = (const float*)d_in[15];
    const float* whh0 = (const float*)d_in[16];
    const float* bih0 = (const float*)d_in[17];
    const float* bhh0 = (const float*)d_in[18];
    const float* wih1 = (const float*)d_in[19];
    const float* whh1 = (const float*)d_in[20];
    const float* bih1 = (const float*)d_in[21];
    const float* bhh1 = (const float*)d_in[22];
    const float* opW1 = (const float*)d_in[23];
    const float* opb1 = (const float*)d_in[24];
    const float* opW2 = (const float*)d_in[25];
    const float* opb2 = (const float*)d_in[26];

    float* out = (float*)d_out;

    cudaFuncSetAttribute(rollout_kernel, cudaFuncAttributeMaxDynamicSharedMemorySize, P_SMEM);

    // scratch addresses
    float *q,*km,*vm,*ctx,*cxt,*pgh,*prior_s;
    cudaGetSymbolAddress((void**)&q, g_q);
    cudaGetSymbolAddress((void**)&km, g_kmem);
    cudaGetSymbolAddress((void**)&vm, g_vmem);
    cudaGetSymbolAddress((void**)&ctx, g_ctx);
    cudaGetSymbolAddress((void**)&cxt, g_context);
    cudaGetSymbolAddress((void**)&pgh, g_pgh);
    cudaGetSymbolAddress((void**)&prior_s, g_prior);

    f16 *xh,*xl,*w0,*wh0,*w1,*wh1,*ow1,*ow2;
    cudaGetSymbolAddress((void**)&xh, g_xh);   cudaGetSymbolAddress((void**)&xl, g_xl);
    cudaGetSymbolAddress((void**)&w0, g_wih0);  cudaGetSymbolAddress((void**)&wh0, g_whh0);
    cudaGetSymbolAddress((void**)&w1, g_wih1);  cudaGetSymbolAddress((void**)&wh1, g_whh1);
    cudaGetSymbolAddress((void**)&ow1, g_opW1); cudaGetSymbolAddress((void**)&ow2, g_opW2);

    bool has_prior_region = (out_size >= PRED_ELEMS + B_*L_);
    float* priorbuf = has_prior_region ? (out + PRED_ELEMS) : prior_s;

    // ---- state init + weight conversion (gate weights permuted to 4j+g order)
    zero_state_kernel<<<(B_*H_ + 255)/256, 256>>>();
    conv_gate_kernel<<<(4*H_*L_ + 255)/256, 256>>>(wih0, w0, L_, 4*H_*L_);
    conv_gate_kernel<<<(4*H_*H_ + 255)/256, 256>>>(whh0, wh0, H_, 4*H_*H_);
    conv_gate_kernel<<<(4*H_*H_ + 255)/256, 256>>>(wih1, w1, H_, 4*H_*H_);
    conv_gate_kernel<<<(4*H_*H_ + 255)/256, 256>>>(whh1, wh1, H_, 4*H_*H_);
    conv_kernel<<<(H_*H_ + 255)/256, 256>>>(opW1, ow1, H_*H_);
    conv_kernel<<<(L_*H_ + 255)/256, 256>>>(opW2, ow2, L_*H_);

    // ---- prologue (fp32) ----
    gemm_small(cs, L_, qW, L_, L_,  nullptr,0,nullptr,0,0, qb,nullptr, q,  H_, B_, H_, 0);
    gemm_small(mem,H_, kW, H_, H_,  nullptr,0,nullptr,0,0, kb,nullptr, km, H_, S_, H_, 0);
    gemm_small(mem,H_, vW, H_, H_,  nullptr,0,nullptr,0,0, vb,nullptr, vm, H_, S_, H_, 0);
    attn_kernel<<<B_, 256>>>(q, km, vm, ctx);
    gemm_small(ctx,H_, moW,H_, H_,  nullptr,0,nullptr,0,0, mob,nullptr, cxt, L_, B_, L_, 0);
    gemm_small(cs, L_, pgW1,      2*L_, L_,
               cxt,L_, pgW1 + L_, 2*L_, L_,
               pgb1, nullptr, pgh, H_, B_, H_, 1);
    gemm_small(pgh,H_, pgW2,H_, H_, nullptr,0,nullptr,0,0, pgb2,nullptr,
               priorbuf, L_, B_, L_, 0);
    split_kernel<<<(B_*L_ + 255)/256, 256>>>(priorbuf, xh, xl, B_*L_);

    // ---- persistent rollout: ONE kernel, 4 phases/step ----
    rollout_kernel<<<256, 128, P_SMEM>>>(bih0, bhh0, bih1, bhh1, opb1, opb2, out);
}

// round 16
// speedup vs baseline: 1.6087x; 1.6087x over previous
#include <cuda_runtime.h>
#include <cuda_fp16.h>
#include <math.h>
#include <stdint.h>

#define B_ 256
#define L_ 512
#define H_ 1024
#define S_ 16
#define HOR_ 64
#define PRED_ELEMS (B_*HOR_*L_)

typedef __half f16;

// ---------------- fp32 scratch ----------------------------------------------
__device__ float g_q[B_*H_];
__device__ float g_kmem[S_*H_];
__device__ float g_vmem[S_*H_];
__device__ float g_ctx[B_*H_];
__device__ float g_context[B_*L_];
__device__ float g_pgh[B_*H_];
__device__ float g_prior[B_*L_];
__device__ float g_c0[B_*H_];
__device__ float g_c1[B_*H_];

// ---------------- fp16 scratch ------------------------------------------------
// x/t: hi+lo (exact). h0/h1: single fp16 (tanh-bounded). weights: single fp16.
__device__ __align__(16) f16 g_xh[B_*L_],  g_xl[B_*L_];
__device__ __align__(16) f16 g_h0[2][B_*H_];
__device__ __align__(16) f16 g_h1[2][B_*H_];
__device__ __align__(16) f16 g_th[B_*H_],  g_tl[B_*H_];
__device__ __align__(16) f16 g_wih0[4*H_*L_];
__device__ __align__(16) f16 g_whh0[4*H_*H_];
__device__ __align__(16) f16 g_wih1[4*H_*H_];
__device__ __align__(16) f16 g_whh1[4*H_*H_];
__device__ __align__(16) f16 g_opW1[H_*H_];
__device__ __align__(16) f16 g_opW2[L_*H_];

// ---------------- hierarchical grid barrier (256 CTAs: 8 x 32) ---------------
__device__ unsigned g_cnt[8*32];
__device__ unsigned g_cnt2 = 0;
__device__ unsigned g_gen  = 0;

// ---------------- low-level helpers ------------------------------------------
__device__ __forceinline__ uint32_t smem_u32(const void* p) {
    uint32_t a;
    asm("{ .reg .u64 t; cvta.to.shared.u64 t, %1; cvt.u32.u64 %0, t; }" : "=r"(a) : "l"(p));
    return a;
}

#define CP_ASYNC16(d, s) \
    asm volatile("cp.async.cg.shared.global [%0], [%1], 16;" :: "r"(d), "l"(s))
#define CP_COMMIT()  asm volatile("cp.async.commit_group;" ::: "memory")

__device__ __forceinline__ void ldm_x4(uint32_t* r, uint32_t addr) {
    asm volatile("ldmatrix.sync.aligned.m8n8.x4.shared.b16 {%0,%1,%2,%3}, [%4];"
                 : "=r"(r[0]), "=r"(r[1]), "=r"(r[2]), "=r"(r[3]) : "r"(addr));
}

__device__ __forceinline__ void mma16816(float* d, const uint32_t* a, const uint32_t* b) {
    asm volatile(
        "mma.sync.aligned.m16n8k16.row.col.f32.f16.f16.f32 "
        "{%0,%1,%2,%3}, {%4,%5,%6,%7}, {%8,%9}, {%0,%1,%2,%3};"
        : "+f"(d[0]), "+f"(d[1]), "+f"(d[2]), "+f"(d[3])
        : "r"(a[0]), "r"(a[1]), "r"(a[2]), "r"(a[3]), "r"(b[0]), "r"(b[1]));
}

__device__ __forceinline__ void grid_sync() {
    __syncthreads();
    if (threadIdx.x == 0) {
        volatile unsigned* genp = (volatile unsigned*)&g_gen;
        const unsigned gen = *genp;
        __threadfence();
        unsigned old = atomicAdd(&g_cnt[(blockIdx.x & 7) * 32], 1u);
        bool flipped = false;
        if (old == 31u) {
            unsigned old2 = atomicAdd(&g_cnt2, 1u);
            if (old2 == 7u) {
                #pragma unroll
                for (int i = 0; i < 8; i++) g_cnt[i * 32] = 0u;
                g_cnt2 = 0u;
                __threadfence();
                *genp = gen + 1u;
                flipped = true;
            }
        }
        if (!flipped) {
            while (*genp == gen) { }
        }
        __threadfence();
    }
    __syncthreads();
}

// ---------------- device GEMM core (dual source, 4 warps as 2x2) -------------
// acc += A1@W1^T (+A1lo@W1^T if LO1) + A2@W2^T (+A2lo@W2^T if LO2)
// LO flags are compile-time -> fully branch-free specializations.
#define PSTRIDE 40
#define P_SMEM (3 * (2*64 + 64) * PSTRIDE * 2)   // 46080 (gates 64x64 config)

template<int BM, int BN, bool LO1, bool LO2>
__device__ __forceinline__ void gemm_dual(
    uint32_t sb, int tid,
    const f16* __restrict__ Ah1, const f16* __restrict__ Al1, int lda1,
    const f16* __restrict__ W1, int ldw1, int nc1,
    const f16* __restrict__ Ah2, const f16* __restrict__ Al2, int lda2,
    const f16* __restrict__ W2, int ldw2, int nc2,
    float (&acc)[BM/32][2*(BN/32)][4])
{
    constexpr int MI  = BM / 32;
    constexpr int NJ  = BN / 32;
    constexpr int AHo = 0;
    constexpr int ALo = BM * PSTRIDE;
    constexpr int Wo  = 2 * BM * PSTRIDE;
    constexpr int STAGE_B = (2 * BM + BN) * PSTRIDE * 2;

    const int lane = tid & 31, wid = tid >> 5;
    const int warp_m = wid >> 1, warp_n = wid & 1;
    const int nc = nc1 + nc2;

    // ---- per-source loaders (compile-time lo flag) ----
    auto load_src = [&](int c, const f16* Ah, const f16* Al, const f16* W,
                        int lda, int ldw, int k0, bool uselo_ct) {
        const uint32_t st = sb + (uint32_t)(c % 3) * STAGE_B;
        // A hi tile: BM rows x 4 chunks
        #pragma unroll
        for (int it = 0; it < (BM * 4) / 128; it++) {
            int idx = tid + it * 128;
            int row = idx >> 2, ch = idx & 3;
            CP_ASYNC16(st + (uint32_t)(AHo + row * PSTRIDE + ch * 8) * 2,
                       Ah + (size_t)row * lda + k0 + ch * 8);
        }
        if (uselo_ct) {
            #pragma unroll
            for (int it = 0; it < (BM * 4) / 128; it++) {
                int idx = tid + it * 128;
                int row = idx >> 2, ch = idx & 3;
                CP_ASYNC16(st + (uint32_t)(ALo + row * PSTRIDE + ch * 8) * 2,
                           Al + (size_t)row * lda + k0 + ch * 8);
            }
        }
        // W tile: BN rows x 4 chunks
        #pragma unroll
        for (int it = 0; it < (BN * 4) / 128; it++) {
            int idx = tid + it * 128;
            int row = idx >> 2, ch = idx & 3;
            CP_ASYNC16(st + (uint32_t)(Wo + row * PSTRIDE + ch * 8) * 2,
                       W + (size_t)row * ldw + k0 + ch * 8);
        }
        CP_COMMIT();
    };

    auto do_load = [&](int c) {
        if (c < nc1) load_src(c, Ah1, Al1, W1, lda1, ldw1, c << 5, LO1);
        else         load_src(c, Ah2, Al2, W2, lda2, ldw2, (c - nc1) << 5, LO2);
    };

    do_load(0);
    if (nc > 1) do_load(1);

    const int a_row = warp_m * (MI * 16) + (lane & 15);
    const int a_kof = (lane >> 4) << 3;
    const int b_row = warp_n * (NJ * 16) + ((lane >> 4) << 3) + (lane & 7);
    const int b_kof = ((lane >> 3) & 1) << 3;

    // ---- compute for one chunk, lo flag compile-time ----
    auto compute = [&](uint32_t st, bool uselo_ct) {
        #pragma unroll
        for (int k16 = 0; k16 < 2; k16++) {
            const int kk = k16 * 16;
            uint32_t ah[MI][4], al[MI][4], bw[NJ][4];
            #pragma unroll
            for (int mi = 0; mi < MI; mi++) {
                ldm_x4(ah[mi], st + (uint32_t)((AHo + (a_row + mi*16) * PSTRIDE + kk + a_kof) * 2));
                if (uselo_ct)
                    ldm_x4(al[mi], st + (uint32_t)((ALo + (a_row + mi*16) * PSTRIDE + kk + a_kof) * 2));
            }
            #pragma unroll
            for (int g = 0; g < NJ; g++)
                ldm_x4(bw[g], st + (uint32_t)((Wo + (b_row + g*16) * PSTRIDE + kk + b_kof) * 2));
            #pragma unroll
            for (int mi = 0; mi < MI; mi++)
                #pragma unroll
                for (int nj = 0; nj < 2*NJ; nj++) {
                    const int g = nj >> 1, o = (nj & 1) * 2;
                    mma16816(acc[mi][nj], ah[mi], &bw[g][o]);
                    if (uselo_ct) mma16816(acc[mi][nj], al[mi], &bw[g][o]);
                }
        }
    };

    // ---- source-1 chunks ----
    for (int c = 0; c < nc1; c++) {
        if (c + 1 < nc) asm volatile("cp.async.wait_group 1;" ::: "memory");
        else            asm volatile("cp.async.wait_group 0;" ::: "memory");
        __syncthreads();
        if (c + 2 < nc) do_load(c + 2);
        compute(sb + (uint32_t)(c % 3) * STAGE_B, LO1);
    }
    // ---- source-2 chunks ----
    for (int c = nc1; c < nc; c++) {
        if (c + 1 < nc) asm volatile("cp.async.wait_group 1;" ::: "memory");
        else            asm volatile("cp.async.wait_group 0;" ::: "memory");
        __syncthreads();
        if (c + 2 < nc) do_load(c + 2);
        compute(sb + (uint32_t)(c % 3) * STAGE_B, LO2);
    }
    __syncthreads();
}

template<int MI, int NJ2>
__device__ __forceinline__ void zero_acc(float (&acc)[MI][NJ2][4]) {
    #pragma unroll
    for (int i = 0; i < MI; i++)
        #pragma unroll
        for (int j = 0; j < NJ2; j++)
            #pragma unroll
            for (int r = 0; r < 4; r++) acc[i][j][r] = 0.f;
}

// fused LSTM cell epilogue (64x64 tiles, warp 32x32; col n = 4*j + gate)
__device__ __forceinline__ void cell_epi(
    float (&acc)[2][4][4], int tid, int m0, int n0,
    const float* __restrict__ b1, const float* __restrict__ b2,
    const float* __restrict__ cin, float* __restrict__ cout,
    f16* __restrict__ Oh)
{
    const int lane = tid & 31, wid = tid >> 5;
    const int warp_m = wid >> 1, warp_n = wid & 1;
    const int m_base = m0 + warp_m * 32;
    const int n_base = n0 + warp_n * 32;
    #pragma unroll
    for (int mi = 0; mi < 2; mi++) {
        #pragma unroll
        for (int nj = 0; nj < 4; nj++) {
            const int c0 = n_base + nj * 8 + (lane & 3) * 2;
            const int bi0 = (c0 & 3) * H_ + (c0 >> 2);
            const int bi1 = ((c0 + 1) & 3) * H_ + ((c0 + 1) >> 2);
            const float bias0 = b1[bi0] + b2[bi0];
            const float bias1 = b1[bi1] + b2[bi1];
            #pragma unroll
            for (int half = 0; half < 2; half++) {
                const int row = m_base + mi * 16 + (lane >> 2) + half * 8;
                float v0 = acc[mi][nj][half*2 + 0] + bias0;
                float v1 = acc[mi][nj][half*2 + 1] + bias1;
                float p0 = __shfl_xor_sync(0xffffffffu, v0, 1);
                float p1 = __shfl_xor_sync(0xffffffffu, v1, 1);
                if ((lane & 1) == 0) {
                    const int j   = c0 >> 2;
                    const int idx = row * H_ + j;
                    float ig = 1.f / (1.f + expf(-v0));
                    float fg = 1.f / (1.f + expf(-v1));
                    float gg = tanhf(p0);
                    float og = 1.f / (1.f + expf(-p1));
                    float cv = fg * cin[idx] + ig * gg;
                    float hv = og * tanhf(cv);
                    cout[idx] = cv;
                    Oh[idx] = __float2half(hv);
                }
            }
        }
    }
}

// standard epilogue: bias (+relu), optional fp32 C, optional fp16 hi/lo split
template<int MI, int NJ>
__device__ __forceinline__ void std_epi(
    float (&acc)[MI][2*NJ][4], int tid, int m0, int n0,
    const float* __restrict__ b,
    float* __restrict__ C, int ldc,
    f16* __restrict__ Oh, f16* __restrict__ Ol, int ldo, int relu)
{
    const int lane = tid & 31, wid = tid >> 5;
    const int warp_m = wid >> 1, warp_n = wid & 1;
    const int m_base = m0 + warp_m * (MI * 16);
    const int n_base = n0 + warp_n * (NJ * 16);
    #pragma unroll
    for (int mi = 0; mi < MI; mi++) {
        #pragma unroll
        for (int nj = 0; nj < 2*NJ; nj++) {
            const int col = n_base + nj * 8 + (lane & 3) * 2;
            const float bias0 = b[col];
            const float bias1 = b[col + 1];
            #pragma unroll
            for (int half = 0; half < 2; half++) {
                const int row = m_base + mi * 16 + (lane >> 2) + half * 8;
                float v0 = acc[mi][nj][half*2 + 0] + bias0;
                float v1 = acc[mi][nj][half*2 + 1] + bias1;
                if (relu) { v0 = fmaxf(v0, 0.f); v1 = fmaxf(v1, 0.f); }
                if (C)
                    *reinterpret_cast<float2*>(C + (size_t)row * ldc + col) =
                        make_float2(v0, v1);
                if (Oh) {
                    f16 h0 = __float2half(v0);
                    f16 h1 = __float2half(v1);
                    f16 l0 = __float2half(v0 - __half2float(h0));
                    f16 l1 = __float2half(v1 - __half2float(h1));
                    f16 hp[2] = {h0, h1}, lp[2] = {l0, l1};
                    *reinterpret_cast<uint32_t*>(Oh + (size_t)row * ldo + col) =
                        *reinterpret_cast<uint32_t*>(hp);
                    *reinterpret_cast<uint32_t*>(Ol + (size_t)row * ldo + col) =
                        *reinterpret_cast<uint32_t*>(lp);
                }
            }
        }
    }
}

// ---------------- persistent rollout kernel ----------------------------------
__global__ void __launch_bounds__(128, 2)
rollout_kernel(const float* __restrict__ bih0, const float* __restrict__ bhh0,
               const float* __restrict__ bih1, const float* __restrict__ bhh1,
               const float* __restrict__ opb1, const float* __restrict__ opb2,
               float* __restrict__ out)
{
    extern __shared__ __align__(16) char smem[];
    const uint32_t sb = smem_u32(smem);
    const int tid = threadIdx.x;
    const int cta = blockIdx.x;

    const int gm0 = (cta & 3) * 64;
    const int gn0 = (cta >> 2) * 64;
    const int o1m = (cta & 7) * 32, o1n = (cta >> 3) * 32;
    const int o2m = (cta & 7) * 32, o2n = (cta >> 3) * 32;

    for (int s = 0; s < HOR_; s++) {
        const int p = s & 1, pn = p ^ 1;

        // ---- phase 1: gates0 (x@wih0 [hi+lo] + h0@whh0 [hi]) + cell ----
        {
            float acc[2][4][4];
            zero_acc(acc);
            gemm_dual<64,64,true,false>(sb, tid,
                g_xh + (size_t)gm0*L_, g_xl + (size_t)gm0*L_, L_,
                g_wih0 + (size_t)gn0*L_, L_, L_/32,
                g_h0[p] + (size_t)gm0*H_, nullptr, H_,
                g_whh0 + (size_t)gn0*H_, H_, H_/32,
                acc);
            cell_epi(acc, tid, gm0, gn0, bih0, bhh0, g_c0, g_c0, g_h0[pn]);
        }
        grid_sync();

        // ---- phase 2: gates1 (h0@wih1 [hi] + h1@whh1 [hi]) + cell ----
        {
            float acc[2][4][4];
            zero_acc(acc);
            gemm_dual<64,64,false,false>(sb, tid,
                g_h0[pn] + (size_t)gm0*H_, nullptr, H_,
                g_wih1 + (size_t)gn0*H_, H_, H_/32,
                g_h1[p] + (size_t)gm0*H_, nullptr, H_,
                g_whh1 + (size_t)gn0*H_, H_, H_/32,
                acc);
            cell_epi(acc, tid, gm0, gn0, bih1, bhh1, g_c1, g_c1, g_h1[pn]);
        }
        grid_sync();

        // ---- phase 3: op1 = relu(h1 @ opW1^T + b1) [hi] -> th/tl ----
        {
            float acc[1][2][4];
            zero_acc(acc);
            gemm_dual<32,32,false,false>(sb, tid,
                g_h1[pn] + (size_t)o1m*H_, nullptr, H_,
                g_opW1 + (size_t)o1n*H_, H_, H_/32,
                nullptr, nullptr, 0, nullptr, 0, 0,
                acc);
            std_epi<1,1>(acc, tid, o1m, o1n, opb1, nullptr, 0, g_th, g_tl, H_, 1);
        }
        grid_sync();

        // ---- phase 4: op2 = t @ opW2^T + b2 [hi+lo] -> out + x split ----
        if (cta < 128) {
            float acc[1][2][4];
            zero_acc(acc);
            gemm_dual<32,32,true,false>(sb, tid,
                g_th + (size_t)o2m*H_, g_tl + (size_t)o2m*H_, H_,
                g_opW2 + (size_t)o2n*H_, H_, H_/32,
                nullptr, nullptr, 0, nullptr, 0, 0,
                acc);
            std_epi<1,1>(acc, tid, o2m, o2n, opb2,
                         out + (size_t)s * L_, HOR_*L_, g_xh, g_xl, L_, 0);
        }
        grid_sync();
    }
}

// ---------------- fp32 GEMM (prologue only) ---------------------------------
template<int BM,int BN,int BK,int TM,int TN,int NT>
__global__ __launch_bounds__(NT)
void gemm2_kernel(const float* __restrict__ A1, int lda1,
                  const float* __restrict__ W1, int ldw1, int K1,
                  const float* __restrict__ A2, int lda2,
                  const float* __restrict__ W2, int ldw2, int K2,
                  const float* __restrict__ b1, const float* __restrict__ b2,
                  float* __restrict__ C, int ldc, int M, int N, int relu)
{
    __shared__ __align__(16) float As[BK][BM+4];
    __shared__ __align__(16) float Ws[BK][BN+4];
    const int tid = threadIdx.x;
    const int m0  = blockIdx.y * BM;
    const int n0  = blockIdx.x * BN;
    const int m0t = (tid / (BN/TN)) * TM;
    const int n0t = (tid % (BN/TN)) * TN;
    float acc[TM][TN];
    #pragma unroll
    for (int i = 0; i < TM; i++)
        #pragma unroll
        for (int j = 0; j < TN; j++) acc[i][j] = 0.f;
    for (int src = 0; src < 2; src++) {
        const float* A = src ? A2 : A1;
        if (A == nullptr) break;
        const float* W = src ? W2 : W1;
        const int lda = src ? lda2 : lda1;
        const int ldw = src ? ldw2 : ldw1;
        const int K   = src ? K2   : K1;
        for (int k0 = 0; k0 < K; k0 += BK) {
            constexpr int A4 = BM*BK/4;
            #pragma unroll
            for (int it = 0; it < A4/NT; it++) {
                int i4 = tid + NT*it;
                int row = i4 / (BK/4), cv = i4 % (BK/4);
                float4 val = make_float4(0,0,0,0);
                int gr = m0 + row;
                if (gr < M) val = *reinterpret_cast<const float4*>(A + (size_t)gr*lda + k0 + cv*4);
                As[cv*4+0][row]=val.x; As[cv*4+1][row]=val.y;
                As[cv*4+2][row]=val.z; As[cv*4+3][row]=val.w;
            }
            constexpr int W4 = BN*BK/4;
            #pragma unroll
            for (int it = 0; it < W4/NT; it++) {
                int i4 = tid + NT*it;
                int row = i4 / (BK/4), cv = i4 % (BK/4);
                float4 val = *reinterpret_cast<const float4*>(W + (size_t)(n0+row)*ldw + k0 + cv*4);
                Ws[cv*4+0][row]=val.x; Ws[cv*4+1][row]=val.y;
                Ws[cv*4+2][row]=val.z; Ws[cv*4+3][row]=val.w;
            }
            __syncthreads();
            #pragma unroll
            for (int kk = 0; kk < BK; kk++) {
                float a[TM], bb[TN];
                #pragma unroll
                for (int i = 0; i < TM; i += 4) {
                    float4 t = *reinterpret_cast<const float4*>(&As[kk][m0t+i]);
                    a[i]=t.x; a[i+1]=t.y; a[i+2]=t.z; a[i+3]=t.w;
                }
                #pragma unroll
                for (int j = 0; j < TN; j += 4) {
                    float4 t = *reinterpret_cast<const float4*>(&Ws[kk][n0t+j]);
                    bb[j]=t.x; bb[j+1]=t.y; bb[j+2]=t.z; bb[j+3]=t.w;
                }
                #pragma unroll
                for (int i = 0; i < TM; i++)
                    #pragma unroll
                    for (int j = 0; j < TN; j++)
                        acc[i][j] = fmaf(a[i], bb[j], acc[i][j]);
            }
            __syncthreads();
        }
    }
    #pragma unroll
    for (int j = 0; j < TN; j++) {
        int gn = n0 + n0t + j;
        float bias = (b1 ? b1[gn] : 0.f) + (b2 ? b2[gn] : 0.f);
        #pragma unroll
        for (int i = 0; i < TM; i++) {
            int gm = m0 + m0t + i;
            if (gm < M) {
                float vo = acc[i][j] + bias;
                if (relu) vo = fmaxf(vo, 0.f);
                C[(size_t)gm*ldc + gn] = vo;
            }
        }
    }
}

// ---------------- attention --------------------------------------------------
__global__ __launch_bounds__(256)
void attn_kernel(const float* __restrict__ q, const float* __restrict__ k,
                 const float* __restrict__ v, float* __restrict__ ctx)
{
    const int b = blockIdx.x, tid = threadIdx.x;
    const int lane = tid & 31, wid = tid >> 5;
    float p[S_];
    #pragma unroll
    for (int s = 0; s < S_; s++) p[s] = 0.f;
    for (int e = tid; e < H_; e += 256) {
        float qv = q[b*H_ + e];
        #pragma unroll
        for (int s = 0; s < S_; s++) p[s] = fmaf(qv, k[s*H_ + e], p[s]);
    }
    #pragma unroll
    for (int s = 0; s < S_; s++)
        #pragma unroll
        for (int off = 16; off > 0; off >>= 1)
            p[s] += __shfl_down_sync(0xffffffffu, p[s], off);
    __shared__ float sred[S_*8];
    __shared__ float wts[S_];
    if (lane == 0)
        #pragma unroll
        for (int s = 0; s < S_; s++) sred[s*8 + wid] = p[s];
    __syncthreads();
    if (tid == 0) {
        float sc[S_]; float mx = -1e30f;
        #pragma unroll
        for (int s = 0; s < S_; s++) {
            float a = 0.f;
            #pragma unroll
            for (int w = 0; w < 8; w++) a += sred[s*8 + w];
            sc[s] = a * (1.0f/32.0f);
            mx = fmaxf(mx, sc[s]);
        }
        float sum = 0.f;
        #pragma unroll
        for (int s = 0; s < S_; s++) { sc[s] = expf(sc[s]-mx); sum += sc[s]; }
        float inv = 1.f/sum;
        #pragma unroll
        for (int s = 0; s < S_; s++) wts[s] = sc[s]*inv;
    }
    __syncthreads();
    for (int j = tid; j < H_; j += 256) {
        float a = 0.f;
        #pragma unroll
        for (int s = 0; s < S_; s++) a = fmaf(wts[s], v[s*H_ + j], a);
        ctx[b*H_ + j] = a;
    }
}

// ---------------- converts ------------------------------------------------------
__global__ __launch_bounds__(256)
void split_kernel(const float* __restrict__ src, f16* __restrict__ hi,
                  f16* __restrict__ lo, int n)
{
    int i = blockIdx.x*blockDim.x + threadIdx.x;
    if (i < n) {
        float v = src[i];
        f16 h = __float2half(v);
        hi[i] = h;
        lo[i] = __float2half(v - __half2float(h));
    }
}

// gate-interleaved fp16 weight convert: out row n = 4*j + g <- in row g*H + j
__global__ __launch_bounds__(256)
void conv_gate_kernel(const float* __restrict__ src, f16* __restrict__ dst,
                      int K, int n)
{
    int i = blockIdx.x*blockDim.x + threadIdx.x;
    if (i < n) {
        int row = i / K, k = i - row * K;
        int orow = (row & 3) * H_ + (row >> 2);
        dst[i] = __float2half(src[(size_t)orow * K + k]);
    }
}

__global__ __launch_bounds__(256)
void conv_kernel(const float* __restrict__ src, f16* __restrict__ dst, int n)
{
    int i = blockIdx.x*blockDim.x + threadIdx.x;
    if (i < n) dst[i] = __float2half(src[i]);
}

__global__ __launch_bounds__(256)
void zero_state_kernel()
{
    int i = blockIdx.x*blockDim.x + threadIdx.x;
    if (i < B_*H_) {
        g_c0[i] = 0.f; g_c1[i] = 0.f;
        f16 z = __float2half(0.f);
        g_h0[0][i] = z; g_h1[0][i] = z;
        g_h0[1][i] = z; g_h1[1][i] = z;
    }
    if (i < 8*32) g_cnt[i] = 0;
    if (i == 0) { g_cnt2 = 0; g_gen = 0; }
}

// ---------------- host helpers -------------------------------------------------
static inline void gemm_small(const float* A1,int lda1,const float* W1,int ldw1,int K1,
                              const float* A2,int lda2,const float* W2,int ldw2,int K2,
                              const float* b1,const float* b2,
                              float* C,int ldc,int M,int N,int relu)
{
    dim3 grid(N/32, (M + 63)/64);
    gemm2_kernel<64,32,16,4,4,128><<<grid,128>>>(A1,lda1,W1,ldw1,K1,
                                                 A2,lda2,W2,ldw2,K2,
                                                 b1,b2,C,ldc,M,N,relu);
}

extern "C" void kernel_launch(void* const* d_in, const int* in_sizes, int n_in,
                              void* d_out, int out_size)
{
    (void)in_sizes; (void)n_in;
    const float* cs   = (const float*)d_in[0];
    const float* mem  = (const float*)d_in[2];
    const float* qW   = (const float*)d_in[3];
    const float* qb   = (const float*)d_in[4];
    const float* kW   = (const float*)d_in[5];
    const float* kb   = (const float*)d_in[6];
    const float* vW   = (const float*)d_in[7];
    const float* vb   = (const float*)d_in[8];
    const float* moW  = (const float*)d_in[9];
    const float* mob  = (const float*)d_in[10];
    const float* pgW1 = (const float*)d_in[11];
    const float* pgb1 = (const float*)d_in[12];
    const float* pgW2 = (const float*)d_in[13];
    const float* pgb2 = (const float*)d_in[14];
    const float* wih0 = (const float*)d_in[15];
    const float* whh0 = (const float*)d_in[16];
    const float* bih0 = (const float*)d_in[17];
    const float* bhh0 = (const float*)d_in[18];
    const float* wih1 = (const float*)d_in[19];
    const float* whh1 = (const float*)d_in[20];
    const float* bih1 = (const float*)d_in[21];
    const float* bhh1 = (const float*)d_in[22];
    const float* opW1 = (const float*)d_in[23];
    const float* opb1 = (const float*)d_in[24];
    const float* opW2 = (const float*)d_in[25];
    const float* opb2 = (const float*)d_in[26];

    float* out = (float*)d_out;

    cudaFuncSetAttribute(rollout_kernel, cudaFuncAttributeMaxDynamicSharedMemorySize, P_SMEM);

    // scratch addresses
    float *q,*km,*vm,*ctx,*cxt,*pgh,*prior_s;
    cudaGetSymbolAddress((void**)&q, g_q);
    cudaGetSymbolAddress((void**)&km, g_kmem);
    cudaGetSymbolAddress((void**)&vm, g_vmem);
    cudaGetSymbolAddress((void**)&ctx, g_ctx);
    cudaGetSymbolAddress((void**)&cxt, g_context);
    cudaGetSymbolAddress((void**)&pgh, g_pgh);
    cudaGetSymbolAddress((void**)&prior_s, g_prior);

    f16 *xh,*xl,*w0,*wh0,*w1,*wh1,*ow1,*ow2;
    cudaGetSymbolAddress((void**)&xh, g_xh);   cudaGetSymbolAddress((void**)&xl, g_xl);
    cudaGetSymbolAddress((void**)&w0, g_wih0);  cudaGetSymbolAddress((void**)&wh0, g_whh0);
    cudaGetSymbolAddress((void**)&w1, g_wih1);  cudaGetSymbolAddress((void**)&wh1, g_whh1);
    cudaGetSymbolAddress((void**)&ow1, g_opW1); cudaGetSymbolAddress((void**)&ow2, g_opW2);

    bool has_prior_region = (out_size >= PRED_ELEMS + B_*L_);
    float* priorbuf = has_prior_region ? (out + PRED_ELEMS) : prior_s;

    // ---- state init + weight conversion (gate weights permuted to 4j+g order)
    zero_state_kernel<<<(B_*H_ + 255)/256, 256>>>();
    conv_gate_kernel<<<(4*H_*L_ + 255)/256, 256>>>(wih0, w0, L_, 4*H_*L_);
    conv_gate_kernel<<<(4*H_*H_ + 255)/256, 256>>>(whh0, wh0, H_, 4*H_*H_);
    conv_gate_kernel<<<(4*H_*H_ + 255)/256, 256>>>(wih1, w1, H_, 4*H_*H_);
    conv_gate_kernel<<<(4*H_*H_ + 255)/256, 256>>>(whh1, wh1, H_, 4*H_*H_);
    conv_kernel<<<(H_*H_ + 255)/256, 256>>>(opW1, ow1, H_*H_);
    conv_kernel<<<(L_*H_ + 255)/256, 256>>>(opW2, ow2, L_*H_);

    // ---- prologue (fp32) ----
    gemm_small(cs, L_, qW, L_, L_,  nullptr,0,nullptr,0,0, qb,nullptr, q,  H_, B_, H_, 0);
    gemm_small(mem,H_, kW, H_, H_,  nullptr,0,nullptr,0,0, kb,nullptr, km, H_, S_, H_, 0);
    gemm_small(mem,H_, vW, H_, H_,  nullptr,0,nullptr,0,0, vb,nullptr, vm, H_, S_, H_, 0);
    attn_kernel<<<B_, 256>>>(q, km, vm, ctx);
    gemm_small(ctx,H_, moW,H_, H_,  nullptr,0,nullptr,0,0, mob,nullptr, cxt, L_, B_, L_, 0);
    gemm_small(cs, L_, pgW1,      2*L_, L_,
               cxt,L_, pgW1 + L_, 2*L_, L_,
               pgb1, nullptr, pgh, H_, B_, H_, 1);
    gemm_small(pgh,H_, pgW2,H_, H_, nullptr,0,nullptr,0,0, pgb2,nullptr,
               priorbuf, L_, B_, L_, 0);
    split_kernel<<<(B_*L_ + 255)/256, 256>>>(priorbuf, xh, xl, B_*L_);

    // ---- persistent rollout: ONE kernel, 4 phases/step ----
    rollout_kernel<<<256, 128, P_SMEM>>>(bih0, bhh0, bih1, bhh1, opb1, opb2, out);
}

// round 17
// speedup vs baseline: 1.7811x; 1.1072x over previous
#include <cuda_runtime.h>
#include <cuda_fp16.h>
#include <math.h>
#include <stdint.h>

#define B_ 256
#define L_ 512
#define H_ 1024
#define S_ 16
#define HOR_ 64
#define PRED_ELEMS (B_*HOR_*L_)

typedef __half f16;

// ---------------- fp32 scratch ----------------------------------------------
__device__ float g_q[B_*H_];
__device__ float g_kmem[S_*H_];
__device__ float g_vmem[S_*H_];
__device__ float g_ctx[B_*H_];
__device__ float g_context[B_*L_];
__device__ float g_pgh[B_*H_];
__device__ float g_prior[B_*L_];
__device__ float g_c0[B_*H_];
__device__ float g_c1[B_*H_];

// ---------------- fp16 scratch ------------------------------------------------
// x/t: hi+lo (exact). h0/h1: single fp16 (tanh-bounded). weights: single fp16.
__device__ __align__(16) f16 g_xh[B_*L_],  g_xl[B_*L_];
__device__ __align__(16) f16 g_h0[2][B_*H_];
__device__ __align__(16) f16 g_h1[2][B_*H_];
__device__ __align__(16) f16 g_th[B_*H_],  g_tl[B_*H_];
__device__ __align__(16) f16 g_wih0[4*H_*L_];
__device__ __align__(16) f16 g_whh0[4*H_*H_];
__device__ __align__(16) f16 g_wih1[4*H_*H_];
__device__ __align__(16) f16 g_whh1[4*H_*H_];
__device__ __align__(16) f16 g_opW1[H_*H_];
__device__ __align__(16) f16 g_opW2[L_*H_];

// ---------------- hierarchical grid barrier (256 CTAs: 8 x 32) ---------------
__device__ unsigned g_cnt[8*32];
__device__ unsigned g_cnt2 = 0;
__device__ unsigned g_gen  = 0;

// ---------------- low-level helpers ------------------------------------------
__device__ __forceinline__ uint32_t smem_u32(const void* p) {
    uint32_t a;
    asm("{ .reg .u64 t; cvta.to.shared.u64 t, %1; cvt.u32.u64 %0, t; }" : "=r"(a) : "l"(p));
    return a;
}

#define CP_ASYNC16(d, s) \
    asm volatile("cp.async.cg.shared.global [%0], [%1], 16;" :: "r"(d), "l"(s))
#define CP_COMMIT()  asm volatile("cp.async.commit_group;" ::: "memory")

__device__ __forceinline__ void ldm_x4(uint32_t* r, uint32_t addr) {
    asm volatile("ldmatrix.sync.aligned.m8n8.x4.shared.b16 {%0,%1,%2,%3}, [%4];"
                 : "=r"(r[0]), "=r"(r[1]), "=r"(r[2]), "=r"(r[3]) : "r"(addr));
}

__device__ __forceinline__ void mma16816(float* d, const uint32_t* a, const uint32_t* b) {
    asm volatile(
        "mma.sync.aligned.m16n8k16.row.col.f32.f16.f16.f32 "
        "{%0,%1,%2,%3}, {%4,%5,%6,%7}, {%8,%9}, {%0,%1,%2,%3};"
        : "+f"(d[0]), "+f"(d[1]), "+f"(d[2]), "+f"(d[3])
        : "r"(a[0]), "r"(a[1]), "r"(a[2]), "r"(a[3]), "r"(b[0]), "r"(b[1]));
}

__device__ __forceinline__ void grid_sync() {
    __syncthreads();
    if (threadIdx.x == 0) {
        volatile unsigned* genp = (volatile unsigned*)&g_gen;
        const unsigned gen = *genp;
        __threadfence();
        unsigned old = atomicAdd(&g_cnt[(blockIdx.x & 7) * 32], 1u);
        bool flipped = false;
        if (old == 31u) {
            unsigned old2 = atomicAdd(&g_cnt2, 1u);
            if (old2 == 7u) {
                #pragma unroll
                for (int i = 0; i < 8; i++) g_cnt[i * 32] = 0u;
                g_cnt2 = 0u;
                __threadfence();
                *genp = gen + 1u;
                flipped = true;
            }
        }
        if (!flipped) {
            while (*genp == gen) { }
        }
        __threadfence();
    }
    __syncthreads();
}

// ---------------- device GEMM core (dual source, 4 warps as 2x2, BK=64) ------
// acc += A1@W1^T (+A1lo@W1^T if LO1) + A2@W2^T (+A2lo@W2^T if LO2)
// LO flags compile-time -> branch-free specializations. Chunks of 64 K-elems.
#define PSTRIDE 72
#define P_SMEM (3 * (2*64 + 64) * PSTRIDE * 2)   // 82944 (gates 64x64 config)

template<int BM, int BN, bool LO1, bool LO2>
__device__ __forceinline__ void gemm_dual(
    uint32_t sb, int tid,
    const f16* __restrict__ Ah1, const f16* __restrict__ Al1, int lda1,
    const f16* __restrict__ W1, int ldw1, int nc1,
    const f16* __restrict__ Ah2, const f16* __restrict__ Al2, int lda2,
    const f16* __restrict__ W2, int ldw2, int nc2,
    float (&acc)[BM/32][2*(BN/32)][4])
{
    constexpr int MI  = BM / 32;
    constexpr int NJ  = BN / 32;
    constexpr int AHo = 0;
    constexpr int ALo = BM * PSTRIDE;
    constexpr int Wo  = 2 * BM * PSTRIDE;
    constexpr int STAGE_B = (2 * BM + BN) * PSTRIDE * 2;

    const int lane = tid & 31, wid = tid >> 5;
    const int warp_m = wid >> 1, warp_n = wid & 1;
    const int nc = nc1 + nc2;

    // ---- per-source loaders (compile-time lo flag); 64 K-elems per chunk ----
    auto load_src = [&](int c, const f16* Ah, const f16* Al, const f16* W,
                        int lda, int ldw, int k0, bool uselo_ct) {
        const uint32_t st = sb + (uint32_t)(c % 3) * STAGE_B;
        // A hi tile: BM rows x 8 16B-chunks
        #pragma unroll
        for (int it = 0; it < (BM * 8) / 128; it++) {
            int idx = tid + it * 128;
            int row = idx >> 3, ch = idx & 7;
            CP_ASYNC16(st + (uint32_t)(AHo + row * PSTRIDE + ch * 8) * 2,
                       Ah + (size_t)row * lda + k0 + ch * 8);
        }
        if (uselo_ct) {
            #pragma unroll
            for (int it = 0; it < (BM * 8) / 128; it++) {
                int idx = tid + it * 128;
                int row = idx >> 3, ch = idx & 7;
                CP_ASYNC16(st + (uint32_t)(ALo + row * PSTRIDE + ch * 8) * 2,
                           Al + (size_t)row * lda + k0 + ch * 8);
            }
        }
        // W tile: BN rows x 8 chunks
        #pragma unroll
        for (int it = 0; it < (BN * 8) / 128; it++) {
            int idx = tid + it * 128;
            int row = idx >> 3, ch = idx & 7;
            CP_ASYNC16(st + (uint32_t)(Wo + row * PSTRIDE + ch * 8) * 2,
                       W + (size_t)row * ldw + k0 + ch * 8);
        }
        CP_COMMIT();
    };

    auto do_load = [&](int c) {
        if (c < nc1) load_src(c, Ah1, Al1, W1, lda1, ldw1, c << 6, LO1);
        else         load_src(c, Ah2, Al2, W2, lda2, ldw2, (c - nc1) << 6, LO2);
    };

    do_load(0);
    if (nc > 1) do_load(1);

    const int a_row = warp_m * (MI * 16) + (lane & 15);
    const int a_kof = (lane >> 4) << 3;
    const int b_row = warp_n * (NJ * 16) + ((lane >> 4) << 3) + (lane & 7);
    const int b_kof = ((lane >> 3) & 1) << 3;

    // ---- compute one 64-wide chunk (4 x k16), lo flag compile-time ----
    auto compute = [&](uint32_t st, bool uselo_ct) {
        #pragma unroll
        for (int k16 = 0; k16 < 4; k16++) {
            const int kk = k16 * 16;
            uint32_t ah[MI][4], al[MI][4], bw[NJ][4];
            #pragma unroll
            for (int mi = 0; mi < MI; mi++) {
                ldm_x4(ah[mi], st + (uint32_t)((AHo + (a_row + mi*16) * PSTRIDE + kk + a_kof) * 2));
                if (uselo_ct)
                    ldm_x4(al[mi], st + (uint32_t)((ALo + (a_row + mi*16) * PSTRIDE + kk + a_kof) * 2));
            }
            #pragma unroll
            for (int g = 0; g < NJ; g++)
                ldm_x4(bw[g], st + (uint32_t)((Wo + (b_row + g*16) * PSTRIDE + kk + b_kof) * 2));
            #pragma unroll
            for (int mi = 0; mi < MI; mi++)
                #pragma unroll
                for (int nj = 0; nj < 2*NJ; nj++) {
                    const int g = nj >> 1, o = (nj & 1) * 2;
                    mma16816(acc[mi][nj], ah[mi], &bw[g][o]);
                    if (uselo_ct) mma16816(acc[mi][nj], al[mi], &bw[g][o]);
                }
        }
    };

    // ---- source-1 chunks ----
    for (int c = 0; c < nc1; c++) {
        if (c + 1 < nc) asm volatile("cp.async.wait_group 1;" ::: "memory");
        else            asm volatile("cp.async.wait_group 0;" ::: "memory");
        __syncthreads();
        if (c + 2 < nc) do_load(c + 2);
        compute(sb + (uint32_t)(c % 3) * STAGE_B, LO1);
    }
    // ---- source-2 chunks ----
    for (int c = nc1; c < nc; c++) {
        if (c + 1 < nc) asm volatile("cp.async.wait_group 1;" ::: "memory");
        else            asm volatile("cp.async.wait_group 0;" ::: "memory");
        __syncthreads();
        if (c + 2 < nc) do_load(c + 2);
        compute(sb + (uint32_t)(c % 3) * STAGE_B, LO2);
    }
    __syncthreads();
}

template<int MI, int NJ2>
__device__ __forceinline__ void zero_acc(float (&acc)[MI][NJ2][4]) {
    #pragma unroll
    for (int i = 0; i < MI; i++)
        #pragma unroll
        for (int j = 0; j < NJ2; j++)
            #pragma unroll
            for (int r = 0; r < 4; r++) acc[i][j][r] = 0.f;
}

// fused LSTM cell epilogue (64x64 tiles, warp 32x32; col n = 4*j + gate)
__device__ __forceinline__ void cell_epi(
    float (&acc)[2][4][4], int tid, int m0, int n0,
    const float* __restrict__ b1, const float* __restrict__ b2,
    const float* __restrict__ cin, float* __restrict__ cout,
    f16* __restrict__ Oh)
{
    const int lane = tid & 31, wid = tid >> 5;
    const int warp_m = wid >> 1, warp_n = wid & 1;
    const int m_base = m0 + warp_m * 32;
    const int n_base = n0 + warp_n * 32;
    #pragma unroll
    for (int mi = 0; mi < 2; mi++) {
        #pragma unroll
        for (int nj = 0; nj < 4; nj++) {
            const int c0 = n_base + nj * 8 + (lane & 3) * 2;
            const int bi0 = (c0 & 3) * H_ + (c0 >> 2);
            const int bi1 = ((c0 + 1) & 3) * H_ + ((c0 + 1) >> 2);
            const float bias0 = b1[bi0] + b2[bi0];
            const float bias1 = b1[bi1] + b2[bi1];
            #pragma unroll
            for (int half = 0; half < 2; half++) {
                const int row = m_base + mi * 16 + (lane >> 2) + half * 8;
                float v0 = acc[mi][nj][half*2 + 0] + bias0;
                float v1 = acc[mi][nj][half*2 + 1] + bias1;
                float p0 = __shfl_xor_sync(0xffffffffu, v0, 1);
                float p1 = __shfl_xor_sync(0xffffffffu, v1, 1);
                if ((lane & 1) == 0) {
                    const int j   = c0 >> 2;
                    const int idx = row * H_ + j;
                    float ig = 1.f / (1.f + expf(-v0));
                    float fg = 1.f / (1.f + expf(-v1));
                    float gg = tanhf(p0);
                    float og = 1.f / (1.f + expf(-p1));
                    float cv = fg * cin[idx] + ig * gg;
                    float hv = og * tanhf(cv);
                    cout[idx] = cv;
                    Oh[idx] = __float2half(hv);
                }
            }
        }
    }
}

// standard epilogue: bias (+relu), optional fp32 C, optional fp16 hi/lo split
template<int MI, int NJ>
__device__ __forceinline__ void std_epi(
    float (&acc)[MI][2*NJ][4], int tid, int m0, int n0,
    const float* __restrict__ b,
    float* __restrict__ C, int ldc,
    f16* __restrict__ Oh, f16* __restrict__ Ol, int ldo, int relu)
{
    const int lane = tid & 31, wid = tid >> 5;
    const int warp_m = wid >> 1, warp_n = wid & 1;
    const int m_base = m0 + warp_m * (MI * 16);
    const int n_base = n0 + warp_n * (NJ * 16);
    #pragma unroll
    for (int mi = 0; mi < MI; mi++) {
        #pragma unroll
        for (int nj = 0; nj < 2*NJ; nj++) {
            const int col = n_base + nj * 8 + (lane & 3) * 2;
            const float bias0 = b[col];
            const float bias1 = b[col + 1];
            #pragma unroll
            for (int half = 0; half < 2; half++) {
                const int row = m_base + mi * 16 + (lane >> 2) + half * 8;
                float v0 = acc[mi][nj][half*2 + 0] + bias0;
                float v1 = acc[mi][nj][half*2 + 1] + bias1;
                if (relu) { v0 = fmaxf(v0, 0.f); v1 = fmaxf(v1, 0.f); }
                if (C)
                    *reinterpret_cast<float2*>(C + (size_t)row * ldc + col) =
                        make_float2(v0, v1);
                if (Oh) {
                    f16 h0 = __float2half(v0);
                    f16 h1 = __float2half(v1);
                    f16 l0 = __float2half(v0 - __half2float(h0));
                    f16 l1 = __float2half(v1 - __half2float(h1));
                    f16 hp[2] = {h0, h1}, lp[2] = {l0, l1};
                    *reinterpret_cast<uint32_t*>(Oh + (size_t)row * ldo + col) =
                        *reinterpret_cast<uint32_t*>(hp);
                    *reinterpret_cast<uint32_t*>(Ol + (size_t)row * ldo + col) =
                        *reinterpret_cast<uint32_t*>(lp);
                }
            }
        }
    }
}

// ---------------- persistent rollout kernel ----------------------------------
__global__ void __launch_bounds__(128, 2)
rollout_kernel(const float* __restrict__ bih0, const float* __restrict__ bhh0,
               const float* __restrict__ bih1, const float* __restrict__ bhh1,
               const float* __restrict__ opb1, const float* __restrict__ opb2,
               float* __restrict__ out)
{
    extern __shared__ __align__(16) char smem[];
    const uint32_t sb = smem_u32(smem);
    const int tid = threadIdx.x;
    const int cta = blockIdx.x;

    const int gm0 = (cta & 3) * 64;
    const int gn0 = (cta >> 2) * 64;
    const int o1m = (cta & 7) * 32, o1n = (cta >> 3) * 32;
    const int o2m = (cta & 7) * 32, o2n = (cta >> 3) * 32;

    for (int s = 0; s < HOR_; s++) {
        const int p = s & 1, pn = p ^ 1;

        // ---- phase 1: gates0 (x@wih0 [hi+lo] + h0@whh0 [hi]) + cell ----
        {
            float acc[2][4][4];
            zero_acc(acc);
            gemm_dual<64,64,true,false>(sb, tid,
                g_xh + (size_t)gm0*L_, g_xl + (size_t)gm0*L_, L_,
                g_wih0 + (size_t)gn0*L_, L_, L_/64,
                g_h0[p] + (size_t)gm0*H_, nullptr, H_,
                g_whh0 + (size_t)gn0*H_, H_, H_/64,
                acc);
            cell_epi(acc, tid, gm0, gn0, bih0, bhh0, g_c0, g_c0, g_h0[pn]);
        }
        grid_sync();

        // ---- phase 2: gates1 (h0@wih1 [hi] + h1@whh1 [hi]) + cell ----
        {
            float acc[2][4][4];
            zero_acc(acc);
            gemm_dual<64,64,false,false>(sb, tid,
                g_h0[pn] + (size_t)gm0*H_, nullptr, H_,
                g_wih1 + (size_t)gn0*H_, H_, H_/64,
                g_h1[p] + (size_t)gm0*H_, nullptr, H_,
                g_whh1 + (size_t)gn0*H_, H_, H_/64,
                acc);
            cell_epi(acc, tid, gm0, gn0, bih1, bhh1, g_c1, g_c1, g_h1[pn]);
        }
        grid_sync();

        // ---- phase 3: op1 = relu(h1 @ opW1^T + b1) [hi] -> th/tl ----
        {
            float acc[1][2][4];
            zero_acc(acc);
            gemm_dual<32,32,false,false>(sb, tid,
                g_h1[pn] + (size_t)o1m*H_, nullptr, H_,
                g_opW1 + (size_t)o1n*H_, H_, H_/64,
                nullptr, nullptr, 0, nullptr, 0, 0,
                acc);
            std_epi<1,1>(acc, tid, o1m, o1n, opb1, nullptr, 0, g_th, g_tl, H_, 1);
        }
        grid_sync();

        // ---- phase 4: op2 = t @ opW2^T + b2 [hi+lo] -> out + x split ----
        if (cta < 128) {
            float acc[1][2][4];
            zero_acc(acc);
            gemm_dual<32,32,true,false>(sb, tid,
                g_th + (size_t)o2m*H_, g_tl + (size_t)o2m*H_, H_,
                g_opW2 + (size_t)o2n*H_, H_, H_/64,
                nullptr, nullptr, 0, nullptr, 0, 0,
                acc);
            std_epi<1,1>(acc, tid, o2m, o2n, opb2,
                         out + (size_t)s * L_, HOR_*L_, g_xh, g_xl, L_, 0);
        }
        grid_sync();
    }
}

// ---------------- fp32 GEMM (prologue only) ---------------------------------
template<int BM,int BN,int BK,int TM,int TN,int NT>
__global__ __launch_bounds__(NT)
void gemm2_kernel(const float* __restrict__ A1, int lda1,
                  const float* __restrict__ W1, int ldw1, int K1,
                  const float* __restrict__ A2, int lda2,
                  const float* __restrict__ W2, int ldw2, int K2,
                  const float* __restrict__ b1, const float* __restrict__ b2,
                  float* __restrict__ C, int ldc, int M, int N, int relu)
{
    __shared__ __align__(16) float As[BK][BM+4];
    __shared__ __align__(16) float Ws[BK][BN+4];
    const int tid = threadIdx.x;
    const int m0  = blockIdx.y * BM;
    const int n0  = blockIdx.x * BN;
    const int m0t = (tid / (BN/TN)) * TM;
    const int n0t = (tid % (BN/TN)) * TN;
    float acc[TM][TN];
    #pragma unroll
    for (int i = 0; i < TM; i++)
        #pragma unroll
        for (int j = 0; j < TN; j++) acc[i][j] = 0.f;
    for (int src = 0; src < 2; src++) {
        const float* A = src ? A2 : A1;
        if (A == nullptr) break;
        const float* W = src ? W2 : W1;
        const int lda = src ? lda2 : lda1;
        const int ldw = src ? ldw2 : ldw1;
        const int K   = src ? K2   : K1;
        for (int k0 = 0; k0 < K; k0 += BK) {
            constexpr int A4 = BM*BK/4;
            #pragma unroll
            for (int it = 0; it < A4/NT; it++) {
                int i4 = tid + NT*it;
                int row = i4 / (BK/4), cv = i4 % (BK/4);
                float4 val = make_float4(0,0,0,0);
                int gr = m0 + row;
                if (gr < M) val = *reinterpret_cast<const float4*>(A + (size_t)gr*lda + k0 + cv*4);
                As[cv*4+0][row]=val.x; As[cv*4+1][row]=val.y;
                As[cv*4+2][row]=val.z; As[cv*4+3][row]=val.w;
            }
            constexpr int W4 = BN*BK/4;
            #pragma unroll
            for (int it = 0; it < W4/NT; it++) {
                int i4 = tid + NT*it;
                int row = i4 / (BK/4), cv = i4 % (BK/4);
                float4 val = *reinterpret_cast<const float4*>(W + (size_t)(n0+row)*ldw + k0 + cv*4);
                Ws[cv*4+0][row]=val.x; Ws[cv*4+1][row]=val.y;
                Ws[cv*4+2][row]=val.z; Ws[cv*4+3][row]=val.w;
            }
            __syncthreads();
            #pragma unroll
            for (int kk = 0; kk < BK; kk++) {
                float a[TM], bb[TN];
                #pragma unroll
                for (int i = 0; i < TM; i += 4) {
                    float4 t = *reinterpret_cast<const float4*>(&As[kk][m0t+i]);
                    a[i]=t.x; a[i+1]=t.y; a[i+2]=t.z; a[i+3]=t.w;
                }
                #pragma unroll
                for (int j = 0; j < TN; j += 4) {
                    float4 t = *reinterpret_cast<const float4*>(&Ws[kk][n0t+j]);
                    bb[j]=t.x; bb[j+1]=t.y; bb[j+2]=t.z; bb[j+3]=t.w;
                }
                #pragma unroll
                for (int i = 0; i < TM; i++)
                    #pragma unroll
                    for (int j = 0; j < TN; j++)
                        acc[i][j] = fmaf(a[i], bb[j], acc[i][j]);
            }
            __syncthreads();
        }
    }
    #pragma unroll
    for (int j = 0; j < TN; j++) {
        int gn = n0 + n0t + j;
        float bias = (b1 ? b1[gn] : 0.f) + (b2 ? b2[gn] : 0.f);
        #pragma unroll
        for (int i = 0; i < TM; i++) {
            int gm = m0 + m0t + i;
            if (gm < M) {
                float vo = acc[i][j] + bias;
                if (relu) vo = fmaxf(vo, 0.f);
                C[(size_t)gm*ldc + gn] = vo;
            }
        }
    }
}

// ---------------- attention --------------------------------------------------
__global__ __launch_bounds__(256)
void attn_kernel(const float* __restrict__ q, const float* __restrict__ k,
                 const float* __restrict__ v, float* __restrict__ ctx)
{
    const int b = blockIdx.x, tid = threadIdx.x;
    const int lane = tid & 31, wid = tid >> 5;
    float p[S_];
    #pragma unroll
    for (int s = 0; s < S_; s++) p[s] = 0.f;
    for (int e = tid; e < H_; e += 256) {
        float qv = q[b*H_ + e];
        #pragma unroll
        for (int s = 0; s < S_; s++) p[s] = fmaf(qv, k[s*H_ + e], p[s]);
    }
    #pragma unroll
    for (int s = 0; s < S_; s++)
        #pragma unroll
        for (int off = 16; off > 0; off >>= 1)
            p[s] += __shfl_down_sync(0xffffffffu, p[s], off);
    __shared__ float sred[S_*8];
    __shared__ float wts[S_];
    if (lane == 0)
        #pragma unroll
        for (int s = 0; s < S_; s++) sred[s*8 + wid] = p[s];
    __syncthreads();
    if (tid == 0) {
        float sc[S_]; float mx = -1e30f;
        #pragma unroll
        for (int s = 0; s < S_; s++) {
            float a = 0.f;
            #pragma unroll
            for (int w = 0; w < 8; w++) a += sred[s*8 + w];
            sc[s] = a * (1.0f/32.0f);
            mx = fmaxf(mx, sc[s]);
        }
        float sum = 0.f;
        #pragma unroll
        for (int s = 0; s < S_; s++) { sc[s] = expf(sc[s]-mx); sum += sc[s]; }
        float inv = 1.f/sum;
        #pragma unroll
        for (int s = 0; s < S_; s++) wts[s] = sc[s]*inv;
    }
    __syncthreads();
    for (int j = tid; j < H_; j += 256) {
        float a = 0.f;
        #pragma unroll
        for (int s = 0; s < S_; s++) a = fmaf(wts[s], v[s*H_ + j], a);
        ctx[b*H_ + j] = a;
    }
}

// ---------------- converts ------------------------------------------------------
__global__ __launch_bounds__(256)
void split_kernel(const float* __restrict__ src, f16* __restrict__ hi,
                  f16* __restrict__ lo, int n)
{
    int i = blockIdx.x*blockDim.x + threadIdx.x;
    if (i < n) {
        float v = src[i];
        f16 h = __float2half(v);
        hi[i] = h;
        lo[i] = __float2half(v - __half2float(h));
    }
}

// gate-interleaved fp16 weight convert: out row n = 4*j + g <- in row g*H + j
__global__ __launch_bounds__(256)
void conv_gate_kernel(const float* __restrict__ src, f16* __restrict__ dst,
                      int K, int n)
{
    int i = blockIdx.x*blockDim.x + threadIdx.x;
    if (i < n) {
        int row = i / K, k = i - row * K;
        int orow = (row & 3) * H_ + (row >> 2);
        dst[i] = __float2half(src[(size_t)orow * K + k]);
    }
}

__global__ __launch_bounds__(256)
void conv_kernel(const float* __restrict__ src, f16* __restrict__ dst, int n)
{
    int i = blockIdx.x*blockDim.x + threadIdx.x;
    if (i < n) dst[i] = __float2half(src[i]);
}

__global__ __launch_bounds__(256)
void zero_state_kernel()
{
    int i = blockIdx.x*blockDim.x + threadIdx.x;
    if (i < B_*H_) {
        g_c0[i] = 0.f; g_c1[i] = 0.f;
        f16 z = __float2half(0.f);
        g_h0[0][i] = z; g_h1[0][i] = z;
        g_h0[1][i] = z; g_h1[1][i] = z;
    }
    if (i < 8*32) g_cnt[i] = 0;
    if (i == 0) { g_cnt2 = 0; g_gen = 0; }
}

// ---------------- host helpers -------------------------------------------------
static inline void gemm_small(const float* A1,int lda1,const float* W1,int ldw1,int K1,
                              const float* A2,int lda2,const float* W2,int ldw2,int K2,
                              const float* b1,const float* b2,
                              float* C,int ldc,int M,int N,int relu)
{
    dim3 grid(N/32, (M + 63)/64);
    gemm2_kernel<64,32,16,4,4,128><<<grid,128>>>(A1,lda1,W1,ldw1,K1,
                                                 A2,lda2,W2,ldw2,K2,
                                                 b1,b2,C,ldc,M,N,relu);
}

extern "C" void kernel_launch(void* const* d_in, const int* in_sizes, int n_in,
                              void* d_out, int out_size)
{
    (void)in_sizes; (void)n_in;
    const float* cs   = (const float*)d_in[0];
    const float* mem  = (const float*)d_in[2];
    const float* qW   = (const float*)d_in[3];
    const float* qb   = (const float*)d_in[4];
    const float* kW   = (const float*)d_in[5];
    const float* kb   = (const float*)d_in[6];
    const float* vW   = (const float*)d_in[7];
    const float* vb   = (const float*)d_in[8];
    const float* moW  = (const float*)d_in[9];
    const float* mob  = (const float*)d_in[10];
    const float* pgW1 = (const float*)d_in[11];
    const float* pgb1 = (const float*)d_in[12];
    const float* pgW2 = (const float*)d_in[13];
    const float* pgb2 = (const float*)d_in[14];
    const float* wih0 = (const float*)d_in[15];
    const float* whh0 = (const float*)d_in[16];
    const float* bih0 = (const float*)d_in[17];
    const float* bhh0 = (const float*)d_in[18];
    const float* wih1 = (const float*)d_in[19];
    const float* whh1 = (const float*)d_in[20];
    const float* bih1 = (const float*)d_in[21];
    const float* bhh1 = (const float*)d_in[22];
    const float* opW1 = (const float*)d_in[23];
    const float* opb1 = (const float*)d_in[24];
    const float* opW2 = (const float*)d_in[25];
    const float* opb2 = (const float*)d_in[26];

    float* out = (float*)d_out;

    cudaFuncSetAttribute(rollout_kernel, cudaFuncAttributeMaxDynamicSharedMemorySize, P_SMEM);

    // scratch addresses
    float *q,*km,*vm,*ctx,*cxt,*pgh,*prior_s;
    cudaGetSymbolAddress((void**)&q, g_q);
    cudaGetSymbolAddress((void**)&km, g_kmem);
    cudaGetSymbolAddress((void**)&vm, g_vmem);
    cudaGetSymbolAddress((void**)&ctx, g_ctx);
    cudaGetSymbolAddress((void**)&cxt, g_context);
    cudaGetSymbolAddress((void**)&pgh, g_pgh);
    cudaGetSymbolAddress((void**)&prior_s, g_prior);

    f16 *xh,*xl,*w0,*wh0,*w1,*wh1,*ow1,*ow2;
    cudaGetSymbolAddress((void**)&xh, g_xh);   cudaGetSymbolAddress((void**)&xl, g_xl);
    cudaGetSymbolAddress((void**)&w0, g_wih0);  cudaGetSymbolAddress((void**)&wh0, g_whh0);
    cudaGetSymbolAddress((void**)&w1, g_wih1);  cudaGetSymbolAddress((void**)&wh1, g_whh1);
    cudaGetSymbolAddress((void**)&ow1, g_opW1); cudaGetSymbolAddress((void**)&ow2, g_opW2);

    bool has_prior_region = (out_size >= PRED_ELEMS + B_*L_);
    float* priorbuf = has_prior_region ? (out + PRED_ELEMS) : prior_s;

    // ---- state init + weight conversion (gate weights permuted to 4j+g order)
    zero_state_kernel<<<(B_*H_ + 255)/256, 256>>>();
    conv_gate_kernel<<<(4*H_*L_ + 255)/256, 256>>>(wih0, w0, L_, 4*H_*L_);
    conv_gate_kernel<<<(4*H_*H_ + 255)/256, 256>>>(whh0, wh0, H_, 4*H_*H_);
    conv_gate_kernel<<<(4*H_*H_ + 255)/256, 256>>>(wih1, w1, H_, 4*H_*H_);
    conv_gate_kernel<<<(4*H_*H_ + 255)/256, 256>>>(whh1, wh1, H_, 4*H_*H_);
    conv_kernel<<<(H_*H_ + 255)/256, 256>>>(opW1, ow1, H_*H_);
    conv_kernel<<<(L_*H_ + 255)/256, 256>>>(opW2, ow2, L_*H_);

    // ---- prologue (fp32) ----
    gemm_small(cs, L_, qW, L_, L_,  nullptr,0,nullptr,0,0, qb,nullptr, q,  H_, B_, H_, 0);
    gemm_small(mem,H_, kW, H_, H_,  nullptr,0,nullptr,0,0, kb,nullptr, km, H_, S_, H_, 0);
    gemm_small(mem,H_, vW, H_, H_,  nullptr,0,nullptr,0,0, vb,nullptr, vm, H_, S_, H_, 0);
    attn_kernel<<<B_, 256>>>(q, km, vm, ctx);
    gemm_small(ctx,H_, moW,H_, H_,  nullptr,0,nullptr,0,0, mob,nullptr, cxt, L_, B_, L_, 0);
    gemm_small(cs, L_, pgW1,      2*L_, L_,
               cxt,L_, pgW1 + L_, 2*L_, L_,
               pgb1, nullptr, pgh, H_, B_, H_, 1);
    gemm_small(pgh,H_, pgW2,H_, H_, nullptr,0,nullptr,0,0, pgb2,nullptr,
               priorbuf, L_, B_, L_, 0);
    split_kernel<<<(B_*L_ + 255)/256, 256>>>(priorbuf, xh, xl, B_*L_);

    // ---- persistent rollout: ONE kernel, 4 phases/step, BK=64 ----
    rollout_kernel<<<256, 128, P_SMEM>>>(bih0, bhh0, bih1, bhh1, opb1, opb2, out);
}